// round 5
// baseline (speedup 1.0000x reference)
#include <cuda_runtime.h>
#include <mma.h>
#include <cstdint>

using namespace nvcuda;

#define HID   1024
#define BATCH 64
#define SEQ   256
#define NGATE 4096
#define NCTA  128
#define WHS_LD 1028

__device__ float g_xg[(size_t)BATCH * SEQ * NGATE];   // [b*SEQ+t][g*HID+k]
// blocked h ring: g_h[slot][kblk*512 + b*8 + kl], kblk = k>>3, kl = k&7
__device__ float g_h[4][BATCH * HID];
__device__ int   g_flag[NCTA];                        // flag[i] = steps published by CTA i (+1)

__device__ __forceinline__ void cp16(void* s, const void* g) {
    uint32_t sa = (uint32_t)__cvta_generic_to_shared(s);
    asm volatile("cp.async.cg.shared.global [%0], [%1], 16;\n" :: "r"(sa), "l"(g));
}
__device__ __forceinline__ void cp_commit() { asm volatile("cp.async.commit_group;\n"); }
template<int N> __device__ __forceinline__ void cp_wait() {
    asm volatile("cp.async.wait_group %0;\n" :: "n"(N));
}
__device__ __forceinline__ float sigm(float x) { return 1.0f / (1.0f + __expf(-x)); }
__device__ __forceinline__ int ld_relaxed(const int* p) {
    int v;
    asm volatile("ld.relaxed.gpu.global.s32 %0, [%1];" : "=r"(v) : "l"(p) : "memory");
    return v;
}

// ------------------------------------------------------------------ phase A
// xg GEMM (M=16384, N=4096, K=1024), tf32 wmma, 128x128x32 tiles, 3-stage cp.async.
// CTA (0,0) additionally performs init (h0 copy into blocked layout + flag seed).
#define BK 32
#define ASMEM (2 * 3 * 128 * 36 * 4)
__global__ void __launch_bounds__(256, 2) gemm_xg_kernel(const float* __restrict__ x,
                                                         const float* __restrict__ Wx,
                                                         const float* __restrict__ h0) {
    extern __shared__ float sm[];
    float* As = sm;                   // [3][128][36]
    float* Bs = sm + 3 * 128 * 36;    // [3][128][36]
    const int tid = threadIdx.x;
    const int wid = tid >> 5;
    const int wm = wid & 3, wn = wid >> 2;
    const int tm = blockIdx.y * 128;
    const int tn = blockIdx.x * 128;

    if (blockIdx.x == 0 && blockIdx.y == 0) {
        // h0 (b-major) -> blocked layout
        for (int i = tid; i < BATCH * HID; i += 256) {
            int b = i >> 10, k = i & 1023;
            g_h[0][(k >> 3) * 512 + b * 8 + (k & 7)] = h0[i];
        }
        __syncthreads();
        __threadfence();
        if (tid < NCTA) g_flag[tid] = 1;   // h(0) published (kernel boundary orders vs lstm)
    }

    wmma::fragment<wmma::accumulator, 16, 16, 8, float> acc[2][4];
    #pragma unroll
    for (int i = 0; i < 2; i++)
        #pragma unroll
        for (int j = 0; j < 4; j++) wmma::fill_fragment(acc[i][j], 0.0f);

    auto issue = [&](int kt) {
        int st = kt % 3;
        int kk = kt * BK;
        float* a = As + st * 128 * 36;
        float* b = Bs + st * 128 * 36;
        #pragma unroll
        for (int i = 0; i < 4; i++) {
            int li = tid + i * 256;  // 0..1023
            int r = li >> 3, sg = li & 7;
            cp16(a + r * 36 + sg * 4, x  + (size_t)(tm + r) * HID + kk + sg * 4);
            cp16(b + r * 36 + sg * 4, Wx + (size_t)(tn + r) * HID + kk + sg * 4);
        }
    };
    issue(0); cp_commit();
    issue(1); cp_commit();

    for (int kt = 0; kt < HID / BK; kt++) {
        cp_wait<1>();
        __syncthreads();
        const int st = kt % 3;
        const float* a = As + st * 128 * 36;
        const float* b = Bs + st * 128 * 36;
        #pragma unroll
        for (int ks = 0; ks < BK / 8; ks++) {
            wmma::fragment<wmma::matrix_a, 16, 16, 8, wmma::precision::tf32, wmma::row_major> af[2];
            wmma::fragment<wmma::matrix_b, 16, 16, 8, wmma::precision::tf32, wmma::col_major> bf[4];
            #pragma unroll
            for (int i = 0; i < 2; i++)
                wmma::load_matrix_sync(af[i], a + (wm * 32 + i * 16) * 36 + ks * 8, 36);
            #pragma unroll
            for (int j = 0; j < 4; j++)
                wmma::load_matrix_sync(bf[j], b + (wn * 64 + j * 16) * 36 + ks * 8, 36);
            #pragma unroll
            for (int i = 0; i < 2; i++)
                #pragma unroll
                for (int j = 0; j < 4; j++)
                    wmma::mma_sync(acc[i][j], af[i], bf[j], acc[i][j]);
        }
        if (kt + 2 < HID / BK) issue(kt + 2);
        cp_commit();
    }
    #pragma unroll
    for (int i = 0; i < 2; i++)
        #pragma unroll
        for (int j = 0; j < 4; j++) {
            size_t r = tm + wm * 32 + i * 16;
            size_t n = tn + wn * 64 + j * 16;
            wmma::store_matrix_sync(g_xg + r * NGATE + n, acc[i][j], NGATE, wmma::mem_row_major);
        }
}

// ------------------------------------------------------------------ phase B (persistent)
#define BSMEM ((32 * WHS_LD + 3 * 64 * 68 + 64 * 36 + 8 * 65 + 32 + 24) * 4)
__global__ void __launch_bounds__(256) lstm_kernel(const float* __restrict__ Wh,
                                                   const float* __restrict__ c0,
                                                   const float* __restrict__ bx,
                                                   const float* __restrict__ bh,
                                                   const float* __restrict__ peep,
                                                   const float* __restrict__ bgate,
                                                   float* __restrict__ out) {
    extern __shared__ float sm[];
    float* Whs = sm;                      // [32][WHS_LD]
    float* hAs = Whs + 32 * WHS_LD;       // [3][64][68]
    float* hgS = hAs + 3 * 64 * 68;       // [64][36]
    float* cS  = hgS + 64 * 36;           // [8][65]
    float* cb  = cS + 8 * 65;             // [32]
    float* ps  = cb + 32;                 // [24]

    const int tid = threadIdx.x;
    const int wid = tid >> 5;
    const int wb = wid & 3, wn = wid >> 2;
    const int k0 = blockIdx.x * 8;

    // one-time staging of this CTA's Wh slice (32 rows x 1024), tf32-rounded
    #pragma unroll 4
    for (int i = 0; i < 32; i++) {
        int li = tid + i * 256;           // float4 idx 0..8191
        int n = li >> 8, sg = li & 255;
        int g = n >> 3, kl = n & 7;
        const float4 v = *(const float4*)(Wh + ((size_t)(g * HID + k0 + kl)) * HID + sg * 4);
        float* d = Whs + n * WHS_LD + sg * 4;
        d[0] = wmma::__float_to_tf32(v.x);
        d[1] = wmma::__float_to_tf32(v.y);
        d[2] = wmma::__float_to_tf32(v.z);
        d[3] = wmma::__float_to_tf32(v.w);
    }
    if (tid < 32) {
        int g = tid >> 3, kl = tid & 7;
        cb[tid] = bx[g * HID + k0 + kl] + bh[g * HID + k0 + kl] + bgate[g * HID + k0 + kl];
    }
    if (tid < 24) ps[tid] = peep[(tid >> 3) * HID + k0 + (tid & 7)];
    #pragma unroll
    for (int rep = 0; rep < 2; rep++) {
        int p = tid + rep * 256;
        int b = p >> 3, kl = p & 7;
        cS[kl * 65 + b] = c0[(size_t)b * HID + k0 + kl];
    }
    __syncthreads();

    for (int t = 0; t < SEQ; t++) {
        // prefetch this step's input-gate preactivations (independent of h_t)
        float xi[2][4];
        #pragma unroll
        for (int rep = 0; rep < 2; rep++) {
            int p = tid + rep * 256;
            int b = p >> 3, kl = p & 7;
            const float* xr = g_xg + (size_t)(b * SEQ + t) * NGATE + k0 + kl;
            xi[rep][0] = __ldg(xr);
            xi[rep][1] = __ldg(xr + HID);
            xi[rep][2] = __ldg(xr + 2 * HID);
            xi[rep][3] = __ldg(xr + 3 * HID);
        }

        // warp 0 polls all 128 producer flags (4 per lane), then acquires
        if (wid == 0) {
            const int* f = g_flag + (tid << 2);
            const int need = t + 1;
            while (true) {
                int a0 = ld_relaxed(f);
                int a1 = ld_relaxed(f + 1);
                int a2 = ld_relaxed(f + 2);
                int a3 = ld_relaxed(f + 3);
                bool ok = (a0 >= need) & (a1 >= need) & (a2 >= need) & (a3 >= need);
                if (__all_sync(0xffffffffu, ok)) break;
            }
            asm volatile("fence.acq_rel.gpu;" ::: "memory");
        }
        __syncthreads();

        const float* hsrc = g_h[t & 3];
        auto issueH = [&](int kc) {
            float* dst = hAs + (kc % 3) * 64 * 68;
            const float* src = hsrc + kc * 4096;    // chunk is contiguous in blocked layout
            #pragma unroll
            for (int i = 0; i < 4; i++) {
                int li = tid + i * 256;   // 0..1023
                int kb = li >> 7;         // local kblk 0..7
                int r  = li & 127;
                int b  = r >> 1;
                int hf = r & 1;
                cp16(dst + b * 68 + kb * 8 + hf * 4, src + kb * 512 + b * 8 + hf * 4);
            }
        };
        issueH(0); cp_commit();
        issueH(1); cp_commit();

        wmma::fragment<wmma::accumulator, 16, 16, 8, float> acc0, acc1;
        wmma::fill_fragment(acc0, 0.0f);
        wmma::fill_fragment(acc1, 0.0f);

        for (int kc = 0; kc < 16; kc++) {
            cp_wait<1>();
            __syncthreads();
            const float* a = hAs + (kc % 3) * 64 * 68;
            #pragma unroll
            for (int ks = 0; ks < 8; ks++) {
                wmma::fragment<wmma::matrix_a, 16, 16, 8, wmma::precision::tf32, wmma::row_major> af;
                wmma::fragment<wmma::matrix_b, 16, 16, 8, wmma::precision::tf32, wmma::col_major> bf;
                wmma::load_matrix_sync(af, a + (wb * 16) * 68 + ks * 8, 68);
                wmma::load_matrix_sync(bf, Whs + (wn * 16) * WHS_LD + kc * 64 + ks * 8, WHS_LD);
                if (ks & 1) wmma::mma_sync(acc1, af, bf, acc1);
                else        wmma::mma_sync(acc0, af, bf, acc0);
            }
            if (kc + 2 < 16) issueH(kc + 2);
            cp_commit();
        }
        #pragma unroll
        for (int e = 0; e < acc0.num_elements; e++) acc0.x[e] += acc1.x[e];
        wmma::store_matrix_sync(hgS + (wb * 16) * 36 + wn * 16, acc0, 36, wmma::mem_row_major);
        __syncthreads();

        // epilogue: gates; h written coalesced (CTA-contiguous 2KB in blocked layout)
        float* hdst = g_h[(t + 1) & 3] + blockIdx.x * 512;
        float hn[2];
        #pragma unroll
        for (int rep = 0; rep < 2; rep++) {
            int p = tid + rep * 256;
            int b = p >> 3, kl = p & 7;
            float c = cS[kl * 65 + b];
            float pi = xi[rep][0] + hgS[b * 36 +      kl] + ps[kl]     * c + cb[kl];
            float pf = xi[rep][1] + hgS[b * 36 +  8 + kl] + ps[8 + kl] * c + cb[8 + kl];
            float pc = xi[rep][2] + hgS[b * 36 + 16 + kl]                  + cb[16 + kl];
            float po = xi[rep][3] + hgS[b * 36 + 24 + kl]                  + cb[24 + kl];
            float cn = sigm(pf) * c + sigm(pi) + tanhf(pc);
            hn[rep] = sigm(po + ps[16 + kl] * cn) * tanhf(cn);
            cS[kl * 65 + b] = cn;
            hdst[p] = hn[rep];
        }
        __syncthreads();                    // all threads' h stores happen-before release
        if (tid == 0)
            asm volatile("st.release.gpu.global.s32 [%0], %1;"
                         :: "l"(g_flag + blockIdx.x), "r"(t + 2) : "memory");

        // out stores AFTER release — off the critical handshake path
        #pragma unroll
        for (int rep = 0; rep < 2; rep++) {
            int p = tid + rep * 256;
            int b = p >> 3, kl = p & 7;
            out[(size_t)(b * SEQ + t) * HID + k0 + kl] = hn[rep];
        }
    }
}

extern "C" void kernel_launch(void* const* d_in, const int* in_sizes, int n_in,
                              void* d_out, int out_size) {
    const float* x     = (const float*)d_in[0];
    const float* h0    = (const float*)d_in[1];
    const float* c0    = (const float*)d_in[2];
    const float* Wx    = (const float*)d_in[3];
    const float* bx    = (const float*)d_in[4];
    const float* Wh    = (const float*)d_in[5];
    const float* bh    = (const float*)d_in[6];
    const float* peep  = (const float*)d_in[7];
    const float* bgate = (const float*)d_in[8];
    float* out = (float*)d_out;

    cudaFuncSetAttribute(gemm_xg_kernel, cudaFuncAttributeMaxDynamicSharedMemorySize, ASMEM);
    cudaFuncSetAttribute(lstm_kernel, cudaFuncAttributeMaxDynamicSharedMemorySize, BSMEM);

    gemm_xg_kernel<<<dim3(32, 128), 256, ASMEM>>>(x, Wx, h0);
    lstm_kernel<<<NCTA, 256, BSMEM>>>(Wh, c0, bx, bh, peep, bgate, out);
}

// round 6
// speedup vs baseline: 2.5607x; 2.5607x over previous
#include <cuda_runtime.h>
#include <cuda_fp16.h>
#include <mma.h>
#include <cstdint>

using namespace nvcuda;

#define HID   1024
#define BATCH 64
#define SEQ   256
#define NGATE 4096
#define NCTA  128
#define WHH_LD 1032

__device__ float  g_xg[(size_t)BATCH * SEQ * NGATE];  // [b*SEQ+t][g*HID+k] fp32
__device__ __half g_xh[(size_t)BATCH * SEQ * HID];    // fp16 x
__device__ __half g_wxh[(size_t)NGATE * HID];         // fp16 Wx
__device__ __half g_whh[(size_t)NGATE * HID];         // fp16 Wh
// blocked h ring (fp16): g_h[slot][kblk*512 + b*8 + kl]
__device__ __half g_h[4][BATCH * HID];
__device__ int    g_cnt8[8];                          // group counters (16 CTAs each)

__device__ __forceinline__ void cp16(void* s, const void* g) {
    uint32_t sa = (uint32_t)__cvta_generic_to_shared(s);
    asm volatile("cp.async.cg.shared.global [%0], [%1], 16;\n" :: "r"(sa), "l"(g));
}
__device__ __forceinline__ void cp_commit() { asm volatile("cp.async.commit_group;\n"); }
template<int N> __device__ __forceinline__ void cp_wait() {
    asm volatile("cp.async.wait_group %0;\n" :: "n"(N));
}
__device__ __forceinline__ float sigm(float x) { return 1.0f / (1.0f + __expf(-x)); }
__device__ __forceinline__ int ld_relaxed(const int* p) {
    int v;
    asm volatile("ld.relaxed.gpu.global.s32 %0, [%1];" : "=r"(v) : "l"(p) : "memory");
    return v;
}

// ------------------------------------------------------------------ convert to fp16
__global__ void convert_kernel(const float* __restrict__ x,
                               const float* __restrict__ Wx,
                               const float* __restrict__ Wh,
                               const float* __restrict__ h0) {
    size_t idx = (size_t)blockIdx.x * blockDim.x + threadIdx.x;
    size_t tot = (size_t)gridDim.x * blockDim.x;
    for (size_t i = idx; i < (size_t)BATCH * SEQ * HID; i += tot) g_xh[i]  = __float2half(x[i]);
    for (size_t i = idx; i < (size_t)NGATE * HID; i += tot)       g_wxh[i] = __float2half(Wx[i]);
    for (size_t i = idx; i < (size_t)NGATE * HID; i += tot)       g_whh[i] = __float2half(Wh[i]);
    for (size_t i = idx; i < (size_t)BATCH * HID; i += tot) {
        int b = (int)(i >> 10), k = (int)(i & 1023);
        g_h[0][(k >> 3) * 512 + b * 8 + (k & 7)] = __float2half(h0[i]);
    }
}

// ------------------------------------------------------------------ phase A
// xg = x * Wx^T  (M=16384, N=4096, K=1024), fp16 wmma m16n16k16, 128x128x32, 3-stage
#define BK 32
#define A_LD 40
#define ASMEM (2 * 3 * 128 * A_LD * 2)
__global__ void __launch_bounds__(256, 2) gemm_xg_kernel() {
    extern __shared__ __half smh[];
    __half* As = smh;                     // [3][128][40]
    __half* Bs = smh + 3 * 128 * A_LD;    // [3][128][40]
    const int tid = threadIdx.x;
    const int wid = tid >> 5;
    const int wm = wid & 3, wn = wid >> 2;
    const int tm = blockIdx.y * 128;
    const int tn = blockIdx.x * 128;

    if (blockIdx.x == 0 && blockIdx.y == 0 && tid < 8) g_cnt8[tid] = 16;  // h(0) published

    wmma::fragment<wmma::accumulator, 16, 16, 16, float> acc[2][4];
    #pragma unroll
    for (int i = 0; i < 2; i++)
        #pragma unroll
        for (int j = 0; j < 4; j++) wmma::fill_fragment(acc[i][j], 0.0f);

    auto issue = [&](int kt) {
        int st = kt % 3;
        int kk = kt * BK;
        __half* a = As + st * 128 * A_LD;
        __half* b = Bs + st * 128 * A_LD;
        #pragma unroll
        for (int i = 0; i < 4; i++) {
            int li = tid + i * 256;          // 0..1023
            int half_sel = li >> 9;          // 0: A, 1: B
            int lj = li & 511;               // 0..511
            int r = lj >> 2, sg = lj & 3;    // row, 16B segment
            if (half_sel == 0)
                cp16(a + r * A_LD + sg * 8, g_xh  + (size_t)(tm + r) * HID + kk + sg * 8);
            else
                cp16(b + r * A_LD + sg * 8, g_wxh + (size_t)(tn + r) * HID + kk + sg * 8);
        }
    };
    issue(0); cp_commit();
    issue(1); cp_commit();

    for (int kt = 0; kt < HID / BK; kt++) {
        cp_wait<1>();
        __syncthreads();
        const int st = kt % 3;
        const __half* a = As + st * 128 * A_LD;
        const __half* b = Bs + st * 128 * A_LD;
        #pragma unroll
        for (int ks = 0; ks < 2; ks++) {
            wmma::fragment<wmma::matrix_a, 16, 16, 16, __half, wmma::row_major> af[2];
            wmma::fragment<wmma::matrix_b, 16, 16, 16, __half, wmma::col_major> bf[4];
            #pragma unroll
            for (int i = 0; i < 2; i++)
                wmma::load_matrix_sync(af[i], a + (wm * 32 + i * 16) * A_LD + ks * 16, A_LD);
            #pragma unroll
            for (int j = 0; j < 4; j++)
                wmma::load_matrix_sync(bf[j], b + (wn * 64 + j * 16) * A_LD + ks * 16, A_LD);
            #pragma unroll
            for (int i = 0; i < 2; i++)
                #pragma unroll
                for (int j = 0; j < 4; j++)
                    wmma::mma_sync(acc[i][j], af[i], bf[j], acc[i][j]);
        }
        if (kt + 2 < HID / BK) issue(kt + 2);
        cp_commit();
    }
    #pragma unroll
    for (int i = 0; i < 2; i++)
        #pragma unroll
        for (int j = 0; j < 4; j++) {
            size_t r = tm + wm * 32 + i * 16;
            size_t n = tn + wn * 64 + j * 16;
            wmma::store_matrix_sync(g_xg + r * NGATE + n, acc[i][j], NGATE, wmma::mem_row_major);
        }
}

// ------------------------------------------------------------------ phase B (persistent)
#define HA_LD 72
#define BSMEM ((32 * WHH_LD + 3 * 64 * HA_LD) * 2 + (64 * 36 + 8 * 65 + 32 + 24) * 4)
__global__ void __launch_bounds__(256) lstm_kernel(const float* __restrict__ c0,
                                                   const float* __restrict__ bx,
                                                   const float* __restrict__ bh,
                                                   const float* __restrict__ peep,
                                                   const float* __restrict__ bgate,
                                                   float* __restrict__ out) {
    extern __shared__ __half smh[];
    __half* Whs = smh;                        // [32][1032] fp16
    __half* hAs = smh + 32 * WHH_LD;          // [3][64][72] fp16
    float*  hgS = (float*)(hAs + 3 * 64 * HA_LD);  // [64][36]
    float*  cS  = hgS + 64 * 36;              // [8][65]
    float*  cb  = cS + 8 * 65;                // [32]
    float*  ps  = cb + 32;                    // [24]

    const int tid = threadIdx.x;
    const int wid = tid >> 5;
    const int wb = wid & 3, wn = wid >> 2;
    const int k0 = blockIdx.x * 8;

    // one-time: stage this CTA's fp16 Wh slice (32 rows x 1024) via cp.async
    #pragma unroll
    for (int i = 0; i < 16; i++) {
        int li = tid + i * 256;               // 0..4095
        int n = li >> 7, sg = li & 127;       // row 0..31, 16B seg 0..127
        int g = n >> 3, kl = n & 7;
        cp16(Whs + n * WHH_LD + sg * 8,
             g_whh + ((size_t)(g * HID + k0 + kl)) * HID + sg * 8);
    }
    cp_commit();
    if (tid < 32) {
        int g = tid >> 3, kl = tid & 7;
        cb[tid] = bx[g * HID + k0 + kl] + bh[g * HID + k0 + kl] + bgate[g * HID + k0 + kl];
    }
    if (tid < 24) ps[tid] = peep[(tid >> 3) * HID + k0 + (tid & 7)];
    #pragma unroll
    for (int rep = 0; rep < 2; rep++) {
        int p = tid + rep * 256;
        int b = p >> 3, kl = p & 7;
        cS[kl * 65 + b] = c0[(size_t)b * HID + k0 + kl];
    }
    cp_wait<0>();
    __syncthreads();

    const int grp = blockIdx.x >> 4;

    for (int t = 0; t < SEQ; t++) {
        // prefetch this step's input-gate preactivations (independent of h_t)
        float xi[2][4];
        #pragma unroll
        for (int rep = 0; rep < 2; rep++) {
            int p = tid + rep * 256;
            int b = p >> 3, kl = p & 7;
            const float* xr = g_xg + (size_t)(b * SEQ + t) * NGATE + k0 + kl;
            xi[rep][0] = __ldg(xr);
            xi[rep][1] = __ldg(xr + HID);
            xi[rep][2] = __ldg(xr + 2 * HID);
            xi[rep][3] = __ldg(xr + 3 * HID);
        }

        // tid0 polls the 8 group counters with backoff, then acquires
        if (tid == 0) {
            const int need = 16 * (t + 1);
            while (true) {
                int m = ld_relaxed(g_cnt8);
                #pragma unroll
                for (int j = 1; j < 8; j++) { int v = ld_relaxed(g_cnt8 + j); m = v < m ? v : m; }
                if (m >= need) break;
                __nanosleep(64);
            }
            asm volatile("fence.acq_rel.gpu;" ::: "memory");
        }
        __syncthreads();

        const __half* hsrc = g_h[t & 3];
        auto issueH = [&](int kc) {
            __half* dst = hAs + (kc % 3) * 64 * HA_LD;
            const __half* src = hsrc + kc * 4096;   // 64 k-elems x 64 batch, contiguous
            #pragma unroll
            for (int i = 0; i < 2; i++) {
                int li = tid + i * 256;   // 0..511
                int kb = li >> 6;         // local kblk 0..7
                int b  = li & 63;
                cp16(dst + b * HA_LD + kb * 8, src + kb * 512 + b * 8);
            }
        };
        issueH(0); cp_commit();
        issueH(1); cp_commit();

        wmma::fragment<wmma::accumulator, 16, 16, 16, float> acc0, acc1;
        wmma::fill_fragment(acc0, 0.0f);
        wmma::fill_fragment(acc1, 0.0f);

        for (int kc = 0; kc < 16; kc++) {
            cp_wait<1>();
            __syncthreads();
            const __half* a = hAs + (kc % 3) * 64 * HA_LD;
            #pragma unroll
            for (int ks = 0; ks < 4; ks++) {
                wmma::fragment<wmma::matrix_a, 16, 16, 16, __half, wmma::row_major> af;
                wmma::fragment<wmma::matrix_b, 16, 16, 16, __half, wmma::col_major> bf;
                wmma::load_matrix_sync(af, a + (wb * 16) * HA_LD + ks * 16, HA_LD);
                wmma::load_matrix_sync(bf, Whs + (wn * 16) * WHH_LD + kc * 64 + ks * 16, WHH_LD);
                if (ks & 1) wmma::mma_sync(acc1, af, bf, acc1);
                else        wmma::mma_sync(acc0, af, bf, acc0);
            }
            if (kc + 2 < 16) issueH(kc + 2);
            cp_commit();
        }
        #pragma unroll
        for (int e = 0; e < acc0.num_elements; e++) acc0.x[e] += acc1.x[e];
        wmma::store_matrix_sync(hgS + (wb * 16) * 36 + wn * 16, acc0, 36, wmma::mem_row_major);
        __syncthreads();

        // epilogue: gates; h written coalesced (1KB contiguous fp16)
        __half* hdst = g_h[(t + 1) & 3] + blockIdx.x * 512;
        float hn[2];
        #pragma unroll
        for (int rep = 0; rep < 2; rep++) {
            int p = tid + rep * 256;
            int b = p >> 3, kl = p & 7;
            float c = cS[kl * 65 + b];
            float pi = xi[rep][0] + hgS[b * 36 +      kl] + ps[kl]     * c + cb[kl];
            float pf = xi[rep][1] + hgS[b * 36 +  8 + kl] + ps[8 + kl] * c + cb[8 + kl];
            float pc = xi[rep][2] + hgS[b * 36 + 16 + kl]                  + cb[16 + kl];
            float po = xi[rep][3] + hgS[b * 36 + 24 + kl]                  + cb[24 + kl];
            float cn = sigm(pf) * c + sigm(pi) + tanhf(pc);
            hn[rep] = sigm(po + ps[16 + kl] * cn) * tanhf(cn);
            cS[kl * 65 + b] = cn;
            hdst[p] = __float2half(hn[rep]);
        }
        __syncthreads();                    // all h stores happen-before the release
        if (tid == 0)
            asm volatile("red.release.gpu.global.add.s32 [%0], %1;"
                         :: "l"(g_cnt8 + grp), "r"(1) : "memory");

        // out stores AFTER release — off the critical handshake path
        #pragma unroll
        for (int rep = 0; rep < 2; rep++) {
            int p = tid + rep * 256;
            int b = p >> 3, kl = p & 7;
            out[(size_t)(b * SEQ + t) * HID + k0 + kl] = hn[rep];
        }
    }
}

extern "C" void kernel_launch(void* const* d_in, const int* in_sizes, int n_in,
                              void* d_out, int out_size) {
    const float* x     = (const float*)d_in[0];
    const float* h0    = (const float*)d_in[1];
    const float* c0    = (const float*)d_in[2];
    const float* Wx    = (const float*)d_in[3];
    const float* bx    = (const float*)d_in[4];
    const float* Wh    = (const float*)d_in[5];
    const float* bh    = (const float*)d_in[6];
    const float* peep  = (const float*)d_in[7];
    const float* bgate = (const float*)d_in[8];
    float* out = (float*)d_out;

    cudaFuncSetAttribute(gemm_xg_kernel, cudaFuncAttributeMaxDynamicSharedMemorySize, ASMEM);
    cudaFuncSetAttribute(lstm_kernel, cudaFuncAttributeMaxDynamicSharedMemorySize, BSMEM);

    convert_kernel<<<1024, 256>>>(x, Wx, Wh, h0);
    gemm_xg_kernel<<<dim3(32, 128), 256, ASMEM>>>();
    lstm_kernel<<<NCTA, 256, BSMEM>>>(c0, bx, bh, peep, bgate, out);
}